// round 10
// baseline (speedup 1.0000x reference)
#include <cuda_runtime.h>
#include <math.h>

#define BB 16
#define MM 60
#define TT 80
#define NA 128
#define NL 64
#define NP 20
#define NLP (NL*NP)        // 1280
#define NTHR 896           // 28 warps: 20 scan + 8 jerk
#define SPB 8              // slices (blocks) per batch
#define NSTG 256           // staged lane points
#define BIGF 3.4e38f

__device__ float g_partial[BB*MM];
__device__ int   g_sync[BB];        // zero-init; selector resets each launch

__global__ __launch_bounds__(NTHR) void fused_kernel(
    const float* __restrict__ mode_logits,
    const float* __restrict__ all_trajs,
    const float* __restrict__ agents_now,
    const float* __restrict__ agents_mask,
    const float* __restrict__ map_lanes,
    const float* __restrict__ lanes_mask,
    float* __restrict__ out,
    int write_idx)
{
    __shared__ __align__(16) float2 s_ag[NA];      // 1 KB
    __shared__ __align__(16) float2 s_ln[NSTG];    // 2 KB
    __shared__ __align__(16) float  s_tj[8*TT*3];  // 30 KB jerk trajectory tiles
    __shared__ int  s_cc[8], s_uc[8];
    __shared__ int  s_last, s_sel;

    const int blk  = blockIdx.x;
    const int b    = blk >> 3;                    // batch
    const int s    = blk & 7;                     // slice
    const int MPB  = (s < 4) ? 8 : 7;
    const int m0   = (s < 4) ? s*8 : 32 + (s-4)*7;
    const int NDT  = MPB * TT;                    // 560 or 640
    const int tid  = threadIdx.x;
    const int w    = tid >> 5;
    const int lane = tid & 31;

    if (tid < 8){ s_cc[tid] = 0; s_uc[tid] = 0; }

    const float* trajb = all_trajs + (size_t)b * MM * TT * 3;

    // ── Warp-0 logits prefetch (softmax precompute later, off the tail)
    float l0 = 0.0f, l1 = -BIGF;
    if (w == 0){
        l0 = mode_logits[b*MM + lane];
        if (lane < MM-32) l1 = mode_logits[b*MM + 32 + lane];
    }

    // ── Ego prefetch (overlaps staging latency)
    float ex = 0.0f, ey = 0.0f;
    if (tid < NDT){
        const float* p = trajb + (size_t)(m0*TT + tid)*3;
        ex = p[0]; ey = p[1];
    }

    // ── Jerk warps: coalesced copy of their mode's 240 floats into shared
    if (w >= 20 && w < 20 + MPB){
        const int wj = w - 20;
        const int m  = m0 + wj;
        const float4* tp  = (const float4*)(trajb + (size_t)m*TT*3);
        float4*       dst = (float4*)(s_tj + wj*TT*3);
        dst[lane] = tp[lane];                     // 60 float4 per mode
        if (lane < 28) dst[32 + lane] = tp[32 + lane];
    }

    // ── Stage agents; invalid -> far away (== +BIG penalty semantics)
    if (tid < NA){
        float valid = agents_mask[b*NA + tid];
        float ax = agents_now[(b*NA + tid)*4 + 0];
        float ay = agents_now[(b*NA + tid)*4 + 1];
        if (valid == 0.0f){ ax = 1e18f; ay = 0.0f; }
        s_ag[tid] = make_float2(ax, ay);
    }
    // ── Stage first NSTG lane points (mask repeats per point)
    if (tid < NSTG){
        float valid = lanes_mask[b*NL + tid/NP];
        const float* src = map_lanes + ((size_t)b*NLP + tid)*3;
        float x = src[0], y = src[1];
        if (valid == 0.0f){ x = 1e18f; y = 0.0f; }
        s_ln[tid] = make_float2(x, y);
    }
    __syncthreads();

    const float4* pa = (const float4*)s_ag;
    const float4* pl = (const float4*)s_ln;

    float js = 0.0f;
    float prob0 = 0.0f, prob1 = 0.0f;             // warp-0 softmax terms
    if (tid < NDT){
        const int ml = tid / TT;

        bool coll = false;   // exists agent with d2 < 4       (min_dist < 2)
        bool near = false;   // exists lane point with d2 <= 9 (min_lane <= 3)

        float a0 = BIGF, a1 = BIGF;
        #pragma unroll 1
        for (int c = 0; c < NA/2; c += 4){        // 8 points/chunk from shared
            #pragma unroll
            for (int k = 0; k < 4; k++){
                float4 p = pa[c+k];
                float dx0 = ex - p.x, dy0 = ey - p.y;
                float dx1 = ex - p.z, dy1 = ey - p.w;
                a0 = fminf(a0, fmaf(dx0, dx0, dy0*dy0));
                a1 = fminf(a1, fmaf(dx1, dx1, dy1*dy1));
            }
            if (fminf(a0, a1) < 4.0f){ coll = true; break; }
        }

        float n0 = BIGF, n1 = BIGF;
        #pragma unroll 1
        for (int c = 0; c < NSTG/2; c += 4){
            #pragma unroll
            for (int k = 0; k < 4; k++){
                float4 p = pl[c+k];
                float dx0 = ex - p.x, dy0 = ey - p.y;
                float dx1 = ex - p.z, dy1 = ey - p.w;
                n0 = fminf(n0, fmaf(dx0, dx0, dy0*dy0));
                n1 = fminf(n1, fmaf(dx1, dx1, dy1*dy1));
            }
            if (fminf(n0, n1) <= 9.0f){ near = true; break; }
        }
        // exact mask-aware global fallback (statistically never taken)
        if (!near){
            #pragma unroll 1
            for (int j = NSTG; j < NLP && !near; j += 8){
                bool hit = false;
                #pragma unroll
                for (int k = 0; k < 8; k++){
                    int jj = j + k;
                    float mv = lanes_mask[b*NL + jj/NP];
                    const float* q = map_lanes + ((size_t)b*NLP + jj)*3;
                    float dx = ex - q[0], dy = ey - q[1];
                    if (mv != 0.0f && fmaf(dx, dx, dy*dy) <= 9.0f) hit = true;
                }
                if (hit) near = true;
            }
        }

        if (coll)  atomicAdd(&s_cc[ml], 1);       // integer -> deterministic
        if (!near) atomicAdd(&s_uc[ml], 1);

        // ── Warp 0: softmax precompute (overlap phase, off the tail)
        if (w == 0){
            float mx = fmaxf(l0, l1);
            #pragma unroll
            for (int d = 16; d; d >>= 1) mx = fmaxf(mx, __shfl_xor_sync(0xffffffffu, mx, d));
            float e0 = __expf(l0 - mx);
            float e1 = (lane < MM-32) ? __expf(l1 - mx) : 0.0f;
            float sum = e0 + e1;
            #pragma unroll
            for (int d = 16; d; d >>= 1) sum += __shfl_xor_sync(0xffffffffu, sum, d);
            sum = __shfl_sync(0xffffffffu, sum, 0);
            prob0 = e0 / sum;
            prob1 = (lane < MM-32) ? e1 / sum : -BIGF;
        }
    }
    else if (w >= 20 && w < 20 + MPB){
        // ── Jerk sums from the shared tile (stride-3 -> conflict-free LDS)
        const float* st = s_tj + (w - 20)*TT*3;
        for (int t = lane; t < TT-3; t += 32){
            float jx = st[t*3+9]  - 3.0f*st[t*3+6] + 3.0f*st[t*3+3] - st[t*3+0];
            float jy = st[t*3+10] - 3.0f*st[t*3+7] + 3.0f*st[t*3+4] - st[t*3+1];
            js += sqrtf(jx*jx + jy*jy);
        }
        #pragma unroll
        for (int d = 16; d; d >>= 1) js += __shfl_xor_sync(0xffffffffu, js, d);
    }
    __syncthreads();

    // ── Publish partial scores for this slice
    if (w >= 20 && w < 20 + MPB && lane == 0){
        const int ml = w - 20;
        const int m  = m0 + ml;
        float comfort   = -js / (float)(TT-3);
        float progress  = trajb[(size_t)(m*TT + TT-1)*3];
        float collision = -(float)s_cc[ml] / (float)TT;
        float drivable  = -(float)s_uc[ml] / (float)TT;
        g_partial[b*MM + m] = 0.1f*comfort + 0.5f*progress
                            + 1.0f*collision + 0.3f*drivable;
    }
    __syncthreads();

    // ── Per-batch handshake (cumulative release fence at tid0)
    if (tid == 0){
        __threadfence();
        int c = atomicAdd(&g_sync[b], 1);
        s_last = (c == SPB-1);
    }
    __syncthreads();
    if (!s_last) return;
    __threadfence();                              // acquire other slices' partials

    // ── Selection (warp 0): add precomputed probs, first-max argmax
    if (w == 0){
        float sc0 = prob0 + g_partial[b*MM + lane];
        float sc1 = (lane < MM-32) ? prob1 + g_partial[b*MM + 32 + lane] : -BIGF;

        float bs; int bi;
        if (sc1 > sc0){ bs = sc1; bi = lane + 32; } else { bs = sc0; bi = lane; }
        #pragma unroll
        for (int d = 16; d; d >>= 1){
            float ov = __shfl_xor_sync(0xffffffffu, bs, d);
            int   oi = __shfl_xor_sync(0xffffffffu, bi, d);
            if (ov > bs || (ov == bs && oi < bi)){ bs = ov; bi = oi; }
        }
        if (lane == 0) s_sel = bi;                // first-max (jnp.argmax tie-break)
    }
    __syncthreads();

    // ── Emit selected trajectory (+ index), reset counter for graph replay
    const int sel = s_sel;
    const float* src = trajb + (size_t)(sel*TT)*3;
    if (tid < TT*3) out[b*TT*3 + tid] = src[tid];
    if (tid == 0){
        if (write_idx) out[BB*TT*3 + b] = (float)sel;
        g_sync[b] = 0;
    }
}

extern "C" void kernel_launch(void* const* d_in, const int* in_sizes, int n_in,
                              void* d_out, int out_size)
{
    const float* mode_logits    = (const float*)d_in[0];
    const float* all_trajs      = (const float*)d_in[1];
    const float* agents_now     = (const float*)d_in[2];
    const float* agents_mask    = (const float*)d_in[3];
    const float* map_lanes      = (const float*)d_in[4];
    const float* map_lanes_mask = (const float*)d_in[5];
    float* out = (float*)d_out;

    int write_idx = (out_size >= BB*TT*3 + BB) ? 1 : 0;

    fused_kernel<<<BB*SPB, NTHR>>>(mode_logits, all_trajs, agents_now, agents_mask,
                                   map_lanes, map_lanes_mask, out, write_idx);
}

// round 11
// speedup vs baseline: 1.3750x; 1.3750x over previous
#include <cuda_runtime.h>
#include <math.h>

#define BB 16
#define MM 60
#define TT 80
#define NA 128
#define NL 64
#define NP 20
#define NLP (NL*NP)        // 1280
#define NTHR 640           // 20 warps; scan + jerk fused per thread
#define SPB 8              // slices (blocks) per batch
#define NSTG 256           // staged lane points
#define NJM (TT-3)         // 77 jerk norms per mode
#define BIGF 3.4e38f

__device__ float g_partial[BB*MM];
__device__ int   g_sync[BB];        // zero-init; selector resets each launch

__global__ __launch_bounds__(NTHR) void fused_kernel(
    const float* __restrict__ mode_logits,
    const float* __restrict__ all_trajs,
    const float* __restrict__ agents_now,
    const float* __restrict__ agents_mask,
    const float* __restrict__ map_lanes,
    const float* __restrict__ lanes_mask,
    float* __restrict__ out,
    int write_idx)
{
    __shared__ __align__(16) float2 s_ag[NA];      // 1 KB
    __shared__ __align__(16) float2 s_ln[NSTG];    // 2 KB
    __shared__ float s_jn[8*NJM];                  // 2.4 KB jerk norms
    __shared__ int   s_cc[8], s_uc[8];
    __shared__ int   s_last, s_sel;

    const int blk  = blockIdx.x;
    const int b    = blk >> 3;                    // batch
    const int s    = blk & 7;                     // slice
    const int MPB  = (s < 4) ? 8 : 7;
    const int m0   = (s < 4) ? s*8 : 32 + (s-4)*7;
    const int NDT  = MPB * TT;                    // 560 or 640 scan tasks
    const int NJT  = MPB * NJM;                   // 539 or 616 jerk tasks
    const int tid  = threadIdx.x;
    const int lane = tid & 31;

    if (tid < 8){ s_cc[tid] = 0; s_uc[tid] = 0; }

    const float* trajb = all_trajs + (size_t)b * MM * TT * 3;

    // ── Ego prefetch (overlaps staging latency)
    float ex = 0.0f, ey = 0.0f;
    if (tid < NDT){
        const float* p = trajb + (size_t)(m0*TT + tid)*3;
        ex = p[0]; ey = p[1];
    }

    // ── Jerk prefetch: thread owns norm (mj, tj); 8 independent LDGs (MLP)
    int   mj = 0, tj = 0;
    float x0=0,x1=0,x2=0,x3=0, y0=0,y1=0,y2=0,y3=0;
    if (tid < NJT){
        mj = tid / NJM; tj = tid - mj*NJM;
        const float* tr = trajb + (size_t)((m0+mj)*TT + tj)*3;
        x0 = tr[0]; x1 = tr[3]; x2 = tr[6]; x3 = tr[9];
        y0 = tr[1]; y1 = tr[4]; y2 = tr[7]; y3 = tr[10];
    }

    // ── Stage agents; invalid -> far away (== +BIG penalty semantics)
    if (tid < NA){
        float valid = agents_mask[b*NA + tid];
        float ax = agents_now[(b*NA + tid)*4 + 0];
        float ay = agents_now[(b*NA + tid)*4 + 1];
        if (valid == 0.0f){ ax = 1e18f; ay = 0.0f; }
        s_ag[tid] = make_float2(ax, ay);
    }
    // ── Stage first NSTG lane points (mask repeats per point)
    if (tid < NSTG){
        float valid = lanes_mask[b*NL + tid/NP];
        const float* src = map_lanes + ((size_t)b*NLP + tid)*3;
        float x = src[0], y = src[1];
        if (valid == 0.0f){ x = 1e18f; y = 0.0f; }
        s_ln[tid] = make_float2(x, y);
    }
    __syncthreads();

    const float4* pa = (const float4*)s_ag;   // 2 points per float4
    const float4* pl = (const float4*)s_ln;

    // ── Distance scans (one task per thread, shared-memory chunks)
    if (tid < NDT){
        const int ml = tid / TT;              // local mode

        bool coll = false;   // exists agent with d2 < 4       (min_dist < 2)
        bool near = false;   // exists lane point with d2 <= 9 (min_lane <= 3)

        float a0 = BIGF, a1 = BIGF;
        #pragma unroll 1
        for (int c = 0; c < NA/2; c += 4){    // 8 points/chunk
            #pragma unroll
            for (int k = 0; k < 4; k++){
                float4 p = pa[c+k];
                float dx0 = ex - p.x, dy0 = ey - p.y;
                float dx1 = ex - p.z, dy1 = ey - p.w;
                a0 = fminf(a0, fmaf(dx0, dx0, dy0*dy0));
                a1 = fminf(a1, fmaf(dx1, dx1, dy1*dy1));
            }
            if (fminf(a0, a1) < 4.0f){ coll = true; break; }
        }

        float n0 = BIGF, n1 = BIGF;
        #pragma unroll 1
        for (int c = 0; c < NSTG/2; c += 4){  // staged fast path
            #pragma unroll
            for (int k = 0; k < 4; k++){
                float4 p = pl[c+k];
                float dx0 = ex - p.x, dy0 = ey - p.y;
                float dx1 = ex - p.z, dy1 = ey - p.w;
                n0 = fminf(n0, fmaf(dx0, dx0, dy0*dy0));
                n1 = fminf(n1, fmaf(dx1, dx1, dy1*dy1));
            }
            if (fminf(n0, n1) <= 9.0f){ near = true; break; }
        }
        // exact mask-aware global fallback, points NSTG..NLP-1 (statistically never)
        if (!near){
            #pragma unroll 1
            for (int j = NSTG; j < NLP && !near; j += 8){
                bool hit = false;
                #pragma unroll
                for (int k = 0; k < 8; k++){
                    int jj = j + k;
                    float mv = lanes_mask[b*NL + jj/NP];
                    const float* q = map_lanes + ((size_t)b*NLP + jj)*3;
                    float dx = ex - q[0], dy = ey - q[1];
                    if (mv != 0.0f && fmaf(dx, dx, dy*dy) <= 9.0f) hit = true;
                }
                if (hit) near = true;
            }
        }

        if (coll)  atomicAdd(&s_cc[ml], 1);   // integer -> deterministic
        if (!near) atomicAdd(&s_uc[ml], 1);
    }

    // ── Jerk norm (loads long since landed), parked in shared
    if (tid < NJT){
        float jx = x3 - 3.0f*x2 + 3.0f*x1 - x0;
        float jy = y3 - 3.0f*y2 + 3.0f*y1 - y0;
        s_jn[mj*NJM + tj] = sqrtf(jx*jx + jy*jy);
    }
    __syncthreads();

    // ── Per-mode partial score: serial fixed-order jerk sum (deterministic)
    if (tid < MPB){
        const int m = m0 + tid;
        const float* jrow = s_jn + tid*NJM;
        float js = 0.0f;
        #pragma unroll 7
        for (int i = 0; i < NJM; i++) js += jrow[i];
        float comfort   = -js / (float)NJM;
        float progress  = trajb[(size_t)(m*TT + TT-1)*3];
        float collision = -(float)s_cc[tid] / (float)TT;
        float drivable  = -(float)s_uc[tid] / (float)TT;
        g_partial[b*MM + m] = 0.1f*comfort + 0.5f*progress
                            + 1.0f*collision + 0.3f*drivable;
        __threadfence();                      // release before counter bump
    }
    __syncthreads();

    // ── Per-batch handshake: 8th arriving slice selects
    if (tid == 0){
        int c = atomicAdd(&g_sync[b], 1);
        s_last = (c == SPB-1);
    }
    __syncthreads();
    if (!s_last) return;
    __threadfence();                          // acquire other slices' partials

    // ── Selection (warp 0): softmax + first-max argmax (byte-for-byte R9)
    if (tid < 32){
        float l0 = mode_logits[b*MM + lane];                                  // m = lane
        float l1 = (lane < MM-32) ? mode_logits[b*MM + 32 + lane] : -BIGF;    // m = lane+32

        float mx = fmaxf(l0, l1);
        #pragma unroll
        for (int d = 16; d; d >>= 1) mx = fmaxf(mx, __shfl_xor_sync(0xffffffffu, mx, d));

        float e0 = __expf(l0 - mx);
        float e1 = (lane < MM-32) ? __expf(l1 - mx) : 0.0f;
        float sum = e0 + e1;
        #pragma unroll
        for (int d = 16; d; d >>= 1) sum += __shfl_xor_sync(0xffffffffu, sum, d);
        sum = __shfl_sync(0xffffffffu, sum, 0);

        float sc0 = e0/sum + g_partial[b*MM + lane];
        float sc1 = (lane < MM-32) ? e1/sum + g_partial[b*MM + 32 + lane] : -BIGF;

        float bs; int bi;
        if (sc1 > sc0){ bs = sc1; bi = lane + 32; } else { bs = sc0; bi = lane; }
        #pragma unroll
        for (int d = 16; d; d >>= 1){
            float ov = __shfl_xor_sync(0xffffffffu, bs, d);
            int   oi = __shfl_xor_sync(0xffffffffu, bi, d);
            if (ov > bs || (ov == bs && oi < bi)){ bs = ov; bi = oi; }
        }
        if (lane == 0) s_sel = bi;            // first-max (jnp.argmax tie-break)
    }
    __syncthreads();

    // ── Emit selected trajectory (+ index), reset counter for graph replay
    const int sel = s_sel;
    const float* src = trajb + (size_t)(sel*TT)*3;
    if (tid < TT*3) out[b*TT*3 + tid] = src[tid];
    if (tid == 0){
        if (write_idx) out[BB*TT*3 + b] = (float)sel;
        g_sync[b] = 0;
    }
}

extern "C" void kernel_launch(void* const* d_in, const int* in_sizes, int n_in,
                              void* d_out, int out_size)
{
    const float* mode_logits    = (const float*)d_in[0];
    const float* all_trajs      = (const float*)d_in[1];
    const float* agents_now     = (const float*)d_in[2];
    const float* agents_mask    = (const float*)d_in[3];
    const float* map_lanes      = (const float*)d_in[4];
    const float* map_lanes_mask = (const float*)d_in[5];
    float* out = (float*)d_out;

    int write_idx = (out_size >= BB*TT*3 + BB) ? 1 : 0;

    fused_kernel<<<BB*SPB, NTHR>>>(mode_logits, all_trajs, agents_now, agents_mask,
                                   map_lanes, map_lanes_mask, out, write_idx);
}

// round 12
// speedup vs baseline: 1.3790x; 1.0029x over previous
#include <cuda_runtime.h>
#include <math.h>
#include <stdint.h>

#define BB 16
#define MM 60
#define TT 80
#define NA 128
#define NL 64
#define NP 20
#define NLP (NL*NP)        // 1280
#define NTHR 640           // 20 warps
#define SPB 8              // slices (CTAs) per batch == cluster size
#define NSTG 256           // staged lane points
#define NJM (TT-3)         // 77 jerk norms per mode
#define TRF (MM*TT*3)      // 14400 floats per batch
#define NPF 23             // prefetch regs per thread (640*23 >= 14400)
#define BIGF 3.4e38f

__device__ __forceinline__ uint32_t smem_u32(const void* p){
    uint32_t a;
    asm("{ .reg .u64 t; cvta.to.shared.u64 t, %1; cvt.u32.u64 %0, t; }"
        : "=r"(a) : "l"(p));
    return a;
}
__device__ __forceinline__ void dsmem_store_rank0(uint32_t local_addr, float v){
    uint32_t rem;
    asm volatile("mapa.shared::cluster.u32 %0, %1, 0;" : "=r"(rem) : "r"(local_addr));
    asm volatile("st.shared::cluster.f32 [%0], %1;" :: "r"(rem), "f"(v) : "memory");
}

__global__ __launch_bounds__(NTHR) __cluster_dims__(SPB, 1, 1)
void fused_kernel(
    const float* __restrict__ mode_logits,
    const float* __restrict__ all_trajs,
    const float* __restrict__ agents_now,
    const float* __restrict__ agents_mask,
    const float* __restrict__ map_lanes,
    const float* __restrict__ lanes_mask,
    float* __restrict__ out,
    int write_idx)
{
    __shared__ __align__(16) float2 s_ag[NA];      // 1 KB
    __shared__ __align__(16) float2 s_ln[NSTG];    // 2 KB
    __shared__ float s_jn[8*NJM];                  // 2.4 KB
    __shared__ float s_part[MM];                   // rank0 receives all 60 partials
    __shared__ int   s_cc[8], s_uc[8];
    __shared__ int   s_sel;

    const int b    = blockIdx.x >> 3;             // batch == cluster id
    uint32_t rank;  asm("mov.u32 %0, %%cluster_ctarank;" : "=r"(rank));
    const int s    = (int)rank;                   // slice
    const int MPB  = (s < 4) ? 8 : 7;
    const int m0   = (s < 4) ? s*8 : 32 + (s-4)*7;
    const int NDT  = MPB * TT;                    // 560 or 640 scan tasks
    const int NJT  = MPB * NJM;                   // 539 or 616 jerk tasks
    const int tid  = threadIdx.x;
    const int lane = tid & 31;

    if (tid < 8){ s_cc[tid] = 0; s_uc[tid] = 0; }

    const float* trajb = all_trajs + (size_t)b * TRF;

    // ── Ego prefetch (overlaps staging latency)
    float ex = 0.0f, ey = 0.0f;
    if (tid < NDT){
        const float* p = trajb + (size_t)(m0*TT + tid)*3;
        ex = p[0]; ey = p[1];
    }

    // ── Jerk prefetch: thread owns norm (mj, tj); 8 independent LDGs (MLP)
    int   mj = 0, tj = 0;
    float x0=0,x1=0,x2=0,x3=0, y0=0,y1=0,y2=0,y3=0;
    if (tid < NJT){
        mj = tid / NJM; tj = tid - mj*NJM;
        const float* tr = trajb + (size_t)((m0+mj)*TT + tj)*3;
        x0 = tr[0]; x1 = tr[3]; x2 = tr[6]; x3 = tr[9];
        y0 = tr[1]; y1 = tr[4]; y2 = tr[7]; y3 = tr[10];
    }

    // ── Stage agents; invalid -> far away (== +BIG penalty semantics)
    if (tid < NA){
        float valid = agents_mask[b*NA + tid];
        float ax = agents_now[(b*NA + tid)*4 + 0];
        float ay = agents_now[(b*NA + tid)*4 + 1];
        if (valid == 0.0f){ ax = 1e18f; ay = 0.0f; }
        s_ag[tid] = make_float2(ax, ay);
    }
    // ── Stage first NSTG lane points (mask repeats per point)
    if (tid < NSTG){
        float valid = lanes_mask[b*NL + tid/NP];
        const float* src = map_lanes + ((size_t)b*NLP + tid)*3;
        float x = src[0], y = src[1];
        if (valid == 0.0f){ x = 1e18f; y = 0.0f; }
        s_ln[tid] = make_float2(x, y);
    }
    __syncthreads();

    const float4* pa = (const float4*)s_ag;   // 2 points per float4
    const float4* pl = (const float4*)s_ln;

    // ── Distance scans (one task per thread, shared-memory chunks)
    if (tid < NDT){
        const int ml = tid / TT;              // local mode

        bool coll = false;   // exists agent with d2 < 4       (min_dist < 2)
        bool near = false;   // exists lane point with d2 <= 9 (min_lane <= 3)

        float a0 = BIGF, a1 = BIGF;
        #pragma unroll 1
        for (int c = 0; c < NA/2; c += 4){
            #pragma unroll
            for (int k = 0; k < 4; k++){
                float4 p = pa[c+k];
                float dx0 = ex - p.x, dy0 = ey - p.y;
                float dx1 = ex - p.z, dy1 = ey - p.w;
                a0 = fminf(a0, fmaf(dx0, dx0, dy0*dy0));
                a1 = fminf(a1, fmaf(dx1, dx1, dy1*dy1));
            }
            if (fminf(a0, a1) < 4.0f){ coll = true; break; }
        }

        float n0 = BIGF, n1 = BIGF;
        #pragma unroll 1
        for (int c = 0; c < NSTG/2; c += 4){
            #pragma unroll
            for (int k = 0; k < 4; k++){
                float4 p = pl[c+k];
                float dx0 = ex - p.x, dy0 = ey - p.y;
                float dx1 = ex - p.z, dy1 = ey - p.w;
                n0 = fminf(n0, fmaf(dx0, dx0, dy0*dy0));
                n1 = fminf(n1, fmaf(dx1, dx1, dy1*dy1));
            }
            if (fminf(n0, n1) <= 9.0f){ near = true; break; }
        }
        // exact mask-aware global fallback, points NSTG..NLP-1 (statistically never)
        if (!near){
            #pragma unroll 1
            for (int j = NSTG; j < NLP && !near; j += 8){
                bool hit = false;
                #pragma unroll
                for (int k = 0; k < 8; k++){
                    int jj = j + k;
                    float mv = lanes_mask[b*NL + jj/NP];
                    const float* q = map_lanes + ((size_t)b*NLP + jj)*3;
                    float dx = ex - q[0], dy = ey - q[1];
                    if (mv != 0.0f && fmaf(dx, dx, dy*dy) <= 9.0f) hit = true;
                }
                if (hit) near = true;
            }
        }

        if (coll)  atomicAdd(&s_cc[ml], 1);   // integer -> deterministic
        if (!near) atomicAdd(&s_uc[ml], 1);
    }

    // ── Jerk norm (loads long since landed), parked in shared
    if (tid < NJT){
        float jx = x3 - 3.0f*x2 + 3.0f*x1 - x0;
        float jy = y3 - 3.0f*y2 + 3.0f*y1 - y0;
        s_jn[mj*NJM + tj] = sqrtf(jx*jx + jy*jy);
    }
    __syncthreads();

    // ── Per-mode partial score -> DSMEM store into rank0's s_part
    if (tid < MPB){
        const int m = m0 + tid;
        const float* jrow = s_jn + tid*NJM;
        float js = 0.0f;
        #pragma unroll 7
        for (int i = 0; i < NJM; i++) js += jrow[i];   // fixed order
        float comfort   = -js / (float)NJM;
        float progress  = trajb[(size_t)(m*TT + TT-1)*3];
        float collision = -(float)s_cc[tid] / (float)TT;
        float drivable  = -(float)s_uc[tid] / (float)TT;
        float part = 0.1f*comfort + 0.5f*progress + 1.0f*collision + 0.3f*drivable;
        dsmem_store_rank0(smem_u32(&s_part[m]), part);
    }

    // ── Rank0: speculative prefetch of ALL candidate trajectories (MLP,
    //    overlaps the cluster wait; consumed after argmax picks sel)
    float pre[NPF];
    if (rank == 0){
        #pragma unroll
        for (int i = 0; i < NPF; i++){
            int idx = tid + i*NTHR;
            pre[i] = (idx < TRF) ? trajb[idx] : 0.0f;
        }
    }

    // ── Cluster barrier: release DSMEM stores, rank0 acquires all partials
    asm volatile("barrier.cluster.arrive.aligned;" ::: "memory");
    asm volatile("barrier.cluster.wait.aligned;"   ::: "memory");
    if (rank != 0) return;

    // ── Selection (rank0 warp 0): softmax + first-max argmax (same math)
    if (tid < 32){
        float l0 = mode_logits[b*MM + lane];                                  // m = lane
        float l1 = (lane < MM-32) ? mode_logits[b*MM + 32 + lane] : -BIGF;    // m = lane+32

        float mx = fmaxf(l0, l1);
        #pragma unroll
        for (int d = 16; d; d >>= 1) mx = fmaxf(mx, __shfl_xor_sync(0xffffffffu, mx, d));

        float e0 = __expf(l0 - mx);
        float e1 = (lane < MM-32) ? __expf(l1 - mx) : 0.0f;
        float sum = e0 + e1;
        #pragma unroll
        for (int d = 16; d; d >>= 1) sum += __shfl_xor_sync(0xffffffffu, sum, d);
        sum = __shfl_sync(0xffffffffu, sum, 0);

        float sc0 = e0/sum + s_part[lane];
        float sc1 = (lane < MM-32) ? e1/sum + s_part[32 + lane] : -BIGF;

        float bs; int bi;
        if (sc1 > sc0){ bs = sc1; bi = lane + 32; } else { bs = sc0; bi = lane; }
        #pragma unroll
        for (int d = 16; d; d >>= 1){
            float ov = __shfl_xor_sync(0xffffffffu, bs, d);
            int   oi = __shfl_xor_sync(0xffffffffu, bi, d);
            if (ov > bs || (ov == bs && oi < bi)){ bs = ov; bi = oi; }
        }
        if (lane == 0) s_sel = bi;            // first-max (jnp.argmax tie-break)
    }
    __syncthreads();

    // ── Emit from prefetched registers: values with mode == sel
    const int lo = s_sel * TT * 3;
    const int hi = lo + TT * 3;
    #pragma unroll
    for (int i = 0; i < NPF; i++){
        int idx = tid + i*NTHR;
        if (idx >= lo && idx < hi) out[b*TT*3 + (idx - lo)] = pre[i];
    }
    if (tid == 0 && write_idx) out[BB*TT*3 + b] = (float)s_sel;
}

extern "C" void kernel_launch(void* const* d_in, const int* in_sizes, int n_in,
                              void* d_out, int out_size)
{
    const float* mode_logits    = (const float*)d_in[0];
    const float* all_trajs      = (const float*)d_in[1];
    const float* agents_now     = (const float*)d_in[2];
    const float* agents_mask    = (const float*)d_in[3];
    const float* map_lanes      = (const float*)d_in[4];
    const float* map_lanes_mask = (const float*)d_in[5];
    float* out = (float*)d_out;

    int write_idx = (out_size >= BB*TT*3 + BB) ? 1 : 0;

    fused_kernel<<<BB*SPB, NTHR>>>(mode_logits, all_trajs, agents_now, agents_mask,
                                   map_lanes, map_lanes_mask, out, write_idx);
}

// round 13
// speedup vs baseline: 1.4077x; 1.0208x over previous
#include <cuda_runtime.h>
#include <math.h>
#include <stdint.h>

#define BB 16
#define MM 60
#define TT 80
#define NA 128
#define NL 64
#define NP 20
#define NLP (NL*NP)        // 1280
#define NTHR 640           // 20 warps
#define SPB 8              // slices (CTAs) per batch == cluster size
#define NSTG 256           // staged lane points
#define NJM (TT-3)         // 77 jerk norms per mode
#define TRF (MM*TT*3)      // 14400 floats per batch
#define NPF 23             // prefetch regs per thread (640*23 >= 14400)
#define BIGF 3.4e38f

__device__ __forceinline__ uint32_t smem_u32(const void* p){
    uint32_t a;
    asm("{ .reg .u64 t; cvta.to.shared.u64 t, %1; cvt.u32.u64 %0, t; }"
        : "=r"(a) : "l"(p));
    return a;
}
__device__ __forceinline__ void dsmem_store_rank0(uint32_t local_addr, float v){
    uint32_t rem;
    asm volatile("mapa.shared::cluster.u32 %0, %1, 0;" : "=r"(rem) : "r"(local_addr));
    asm volatile("st.shared::cluster.f32 [%0], %1;" :: "r"(rem), "f"(v) : "memory");
}

__global__ __launch_bounds__(NTHR) __cluster_dims__(SPB, 1, 1)
void fused_kernel(
    const float* __restrict__ mode_logits,
    const float* __restrict__ all_trajs,
    const float* __restrict__ agents_now,
    const float* __restrict__ agents_mask,
    const float* __restrict__ map_lanes,
    const float* __restrict__ lanes_mask,
    float* __restrict__ out,
    int write_idx)
{
    __shared__ __align__(16) float2 s_ag[NA];      // 1 KB
    __shared__ __align__(16) float2 s_ln[NSTG];    // 2 KB
    __shared__ float s_jn[8*NJM];                  // 2.4 KB
    __shared__ float s_part[MM];                   // rank0 receives all 60 partials
    __shared__ int   s_cc[8], s_uc[8];
    __shared__ int   s_sel;

    const int b    = blockIdx.x >> 3;             // batch == cluster id
    uint32_t rank;  asm("mov.u32 %0, %%cluster_ctarank;" : "=r"(rank));
    const int s    = (int)rank;                   // slice
    const int MPB  = (s < 4) ? 8 : 7;
    const int m0   = (s < 4) ? s*8 : 32 + (s-4)*7;
    const int NDT  = MPB * TT;                    // 560 or 640 scan tasks
    const int NJT  = MPB * NJM;                   // 539 or 616 jerk tasks
    const int tid  = threadIdx.x;
    const int lane = tid & 31;

    if (tid < 8){ s_cc[tid] = 0; s_uc[tid] = 0; }

    const float* trajb = all_trajs + (size_t)b * TRF;

    // ── Rank0 warp0: logits prefetch (softmax computed pre-barrier, off tail)
    float l0 = 0.0f, l1 = -BIGF;
    const bool selwarp = (rank == 0) && (tid < 32);
    if (selwarp){
        l0 = mode_logits[b*MM + lane];
        if (lane < MM-32) l1 = mode_logits[b*MM + 32 + lane];
    }

    // ── Ego prefetch (overlaps staging latency)
    float ex = 0.0f, ey = 0.0f;
    if (tid < NDT){
        const float* p = trajb + (size_t)(m0*TT + tid)*3;
        ex = p[0]; ey = p[1];
    }

    // ── Progress prefetch (removes dependent LDG from the score block)
    float prog = 0.0f;
    if (tid < MPB) prog = trajb[(size_t)((m0 + tid)*TT + TT-1)*3];

    // ── Jerk prefetch: thread owns norm (mj, tj); 8 independent LDGs (MLP)
    int   mj = 0, tj = 0;
    float x0=0,x1=0,x2=0,x3=0, y0=0,y1=0,y2=0,y3=0;
    if (tid < NJT){
        mj = tid / NJM; tj = tid - mj*NJM;
        const float* tr = trajb + (size_t)((m0+mj)*TT + tj)*3;
        x0 = tr[0]; x1 = tr[3]; x2 = tr[6]; x3 = tr[9];
        y0 = tr[1]; y1 = tr[4]; y2 = tr[7]; y3 = tr[10];
    }

    // ── Stage agents; invalid -> far away (== +BIG penalty semantics)
    if (tid < NA){
        float valid = agents_mask[b*NA + tid];
        float ax = agents_now[(b*NA + tid)*4 + 0];
        float ay = agents_now[(b*NA + tid)*4 + 1];
        if (valid == 0.0f){ ax = 1e18f; ay = 0.0f; }
        s_ag[tid] = make_float2(ax, ay);
    }
    // ── Stage first NSTG lane points (mask repeats per point)
    if (tid < NSTG){
        float valid = lanes_mask[b*NL + tid/NP];
        const float* src = map_lanes + ((size_t)b*NLP + tid)*3;
        float x = src[0], y = src[1];
        if (valid == 0.0f){ x = 1e18f; y = 0.0f; }
        s_ln[tid] = make_float2(x, y);
    }
    __syncthreads();

    const float4* pa = (const float4*)s_ag;   // 2 points per float4
    const float4* pl = (const float4*)s_ln;

    // ── Distance scans (one task per thread, shared-memory chunks)
    if (tid < NDT){
        const int ml = tid / TT;              // local mode

        bool coll = false;   // exists agent with d2 < 4       (min_dist < 2)
        bool near = false;   // exists lane point with d2 <= 9 (min_lane <= 3)

        float a0 = BIGF, a1 = BIGF;
        #pragma unroll 1
        for (int c = 0; c < NA/2; c += 4){
            #pragma unroll
            for (int k = 0; k < 4; k++){
                float4 p = pa[c+k];
                float dx0 = ex - p.x, dy0 = ey - p.y;
                float dx1 = ex - p.z, dy1 = ey - p.w;
                a0 = fminf(a0, fmaf(dx0, dx0, dy0*dy0));
                a1 = fminf(a1, fmaf(dx1, dx1, dy1*dy1));
            }
            if (fminf(a0, a1) < 4.0f){ coll = true; break; }
        }

        float n0 = BIGF, n1 = BIGF;
        #pragma unroll 1
        for (int c = 0; c < NSTG/2; c += 4){
            #pragma unroll
            for (int k = 0; k < 4; k++){
                float4 p = pl[c+k];
                float dx0 = ex - p.x, dy0 = ey - p.y;
                float dx1 = ex - p.z, dy1 = ey - p.w;
                n0 = fminf(n0, fmaf(dx0, dx0, dy0*dy0));
                n1 = fminf(n1, fmaf(dx1, dx1, dy1*dy1));
            }
            if (fminf(n0, n1) <= 9.0f){ near = true; break; }
        }
        // exact mask-aware global fallback, points NSTG..NLP-1 (statistically never)
        if (!near){
            #pragma unroll 1
            for (int j = NSTG; j < NLP && !near; j += 8){
                bool hit = false;
                #pragma unroll
                for (int k = 0; k < 8; k++){
                    int jj = j + k;
                    float mv = lanes_mask[b*NL + jj/NP];
                    const float* q = map_lanes + ((size_t)b*NLP + jj)*3;
                    float dx = ex - q[0], dy = ey - q[1];
                    if (mv != 0.0f && fmaf(dx, dx, dy*dy) <= 9.0f) hit = true;
                }
                if (hit) near = true;
            }
        }

        if (coll)  atomicAdd(&s_cc[ml], 1);   // integer -> deterministic
        if (!near) atomicAdd(&s_uc[ml], 1);
    }

    // ── Jerk norm (loads long since landed), parked in shared
    if (tid < NJT){
        float jx = x3 - 3.0f*x2 + 3.0f*x1 - x0;
        float jy = y3 - 3.0f*y2 + 3.0f*y1 - y0;
        s_jn[mj*NJM + tj] = sqrtf(jx*jx + jy*jy);
    }

    // ── Rank0 warp0: softmax precompute (pre-barrier, off the tail)
    float prob0 = 0.0f, prob1 = -BIGF;
    if (selwarp){
        float mx = fmaxf(l0, l1);
        #pragma unroll
        for (int d = 16; d; d >>= 1) mx = fmaxf(mx, __shfl_xor_sync(0xffffffffu, mx, d));
        float e0 = __expf(l0 - mx);
        float e1 = (lane < MM-32) ? __expf(l1 - mx) : 0.0f;
        float sum = e0 + e1;
        #pragma unroll
        for (int d = 16; d; d >>= 1) sum += __shfl_xor_sync(0xffffffffu, sum, d);
        sum = __shfl_sync(0xffffffffu, sum, 0);
        prob0 = e0 / sum;
        prob1 = (lane < MM-32) ? e1 / sum : -BIGF;
    }
    __syncthreads();

    // ── Per-mode partial score -> DSMEM store into rank0's s_part
    //    (4 interleaved accumulators: fixed association, deterministic)
    if (tid < MPB){
        const int m = m0 + tid;
        const float* jrow = s_jn + tid*NJM;
        float a = 0.0f, bb2 = 0.0f, c2 = 0.0f, d2 = 0.0f;
        int i = 0;
        #pragma unroll 4
        for (; i + 3 < NJM; i += 4){
            a   += jrow[i];   bb2 += jrow[i+1];
            c2  += jrow[i+2]; d2  += jrow[i+3];
        }
        for (; i < NJM; i++) a += jrow[i];
        float js = (a + bb2) + (c2 + d2);
        float comfort   = -js / (float)NJM;
        float collision = -(float)s_cc[tid] / (float)TT;
        float drivable  = -(float)s_uc[tid] / (float)TT;
        float part = 0.1f*comfort + 0.5f*prog + 1.0f*collision + 0.3f*drivable;
        dsmem_store_rank0(smem_u32(&s_part[m]), part);
    }

    // ── Rank0: speculative prefetch of ALL candidate trajectories (MLP,
    //    overlaps the cluster wait; consumed after argmax picks sel)
    float pre[NPF];
    if (rank == 0){
        #pragma unroll
        for (int i = 0; i < NPF; i++){
            int idx = tid + i*NTHR;
            pre[i] = (idx < TRF) ? trajb[idx] : 0.0f;
        }
    }

    // ── Cluster barrier: release DSMEM stores, rank0 acquires all partials
    asm volatile("barrier.cluster.arrive.aligned;" ::: "memory");
    asm volatile("barrier.cluster.wait.aligned;"   ::: "memory");
    if (rank != 0) return;

    // ── Selection (rank0 warp0): add precomputed probs, first-max argmax
    if (tid < 32){
        float sc0 = prob0 + s_part[lane];
        float sc1 = (lane < MM-32) ? prob1 + s_part[32 + lane] : -BIGF;

        float bs; int bi;
        if (sc1 > sc0){ bs = sc1; bi = lane + 32; } else { bs = sc0; bi = lane; }
        #pragma unroll
        for (int d = 16; d; d >>= 1){
            float ov = __shfl_xor_sync(0xffffffffu, bs, d);
            int   oi = __shfl_xor_sync(0xffffffffu, bi, d);
            if (ov > bs || (ov == bs && oi < bi)){ bs = ov; bi = oi; }
        }
        if (lane == 0) s_sel = bi;            // first-max (jnp.argmax tie-break)
    }
    __syncthreads();

    // ── Emit from prefetched registers: values with mode == sel
    const int lo = s_sel * TT * 3;
    const int hi = lo + TT * 3;
    #pragma unroll
    for (int i = 0; i < NPF; i++){
        int idx = tid + i*NTHR;
        if (idx >= lo && idx < hi) out[b*TT*3 + (idx - lo)] = pre[i];
    }
    if (tid == 0 && write_idx) out[BB*TT*3 + b] = (float)s_sel;
}

extern "C" void kernel_launch(void* const* d_in, const int* in_sizes, int n_in,
                              void* d_out, int out_size)
{
    const float* mode_logits    = (const float*)d_in[0];
    const float* all_trajs      = (const float*)d_in[1];
    const float* agents_now     = (const float*)d_in[2];
    const float* agents_mask    = (const float*)d_in[3];
    const float* map_lanes      = (const float*)d_in[4];
    const float* map_lanes_mask = (const float*)d_in[5];
    float* out = (float*)d_out;

    int write_idx = (out_size >= BB*TT*3 + BB) ? 1 : 0;

    fused_kernel<<<BB*SPB, NTHR>>>(mode_logits, all_trajs, agents_now, agents_mask,
                                   map_lanes, map_lanes_mask, out, write_idx);
}